// round 2
// baseline (speedup 1.0000x reference)
#include <cuda_runtime.h>
#include <math.h>

// Problem constants
#define N_NODES 200000
#define E_EDGES 200000
#define H 256
#define KDIM 512     // combined K: [x | h_sum]
#define JDIM 1024    // combined output cols: [iou(768) | f(256)]

// Scratch (static __device__ allocations — no cudaMalloc anywhere)
__device__ float g_hsum[(size_t)N_NODES * H];      // 204.8 MB
__device__ float g_csum[(size_t)N_NODES * H];      // 204.8 MB
__device__ float g_pre [(size_t)N_NODES * JDIM];   // 819.2 MB
__device__ float g_B   [JDIM * KDIM];              // 2 MB combined weights

// ---------------------------------------------------------------------------
// 1) Build combined weight matrix B[j,k], row-major [1024,512]:
//    j <  768: k<256 -> W_iou[j,k]        else U_iou[j,k-256]
//    j >= 768: k<256 -> 0                 else U_f_w[j-768,k-256]
// ---------------------------------------------------------------------------
__global__ void build_B_kernel(const float* __restrict__ W_iou,
                               const float* __restrict__ U_iou,
                               const float* __restrict__ U_f_w) {
    int idx = blockIdx.x * blockDim.x + threadIdx.x;
    if (idx >= JDIM * KDIM) return;
    int j = idx / KDIM;
    int k = idx % KDIM;
    float v;
    if (j < 768) {
        v = (k < 256) ? W_iou[j * 256 + k] : U_iou[j * 256 + (k - 256)];
    } else {
        v = (k < 256) ? 0.0f : U_f_w[(j - 768) * 256 + (k - 256)];
    }
    g_B[idx] = v;
}

// ---------------------------------------------------------------------------
// 2) Zero the segment-sum accumulators (float4)
// ---------------------------------------------------------------------------
__global__ void zero_sums_kernel() {
    size_t i = (size_t)blockIdx.x * blockDim.x + threadIdx.x;
    size_t n4 = (size_t)N_NODES * H / 4;
    if (i < n4) {
        ((float4*)g_hsum)[i] = make_float4(0.f, 0.f, 0.f, 0.f);
        ((float4*)g_csum)[i] = make_float4(0.f, 0.f, 0.f, 0.f);
    }
}

// ---------------------------------------------------------------------------
// 3) Scatter-add: for each edge e, g_hsum[dst[e]] += h[src[e]] (and c).
//    One thread per (edge, float4-chunk): E*64 threads, 8 atomics each.
// ---------------------------------------------------------------------------
__global__ void scatter_kernel(const float* __restrict__ h,
                               const float* __restrict__ c,
                               const int* __restrict__ src,
                               const int* __restrict__ dst) {
    size_t t = (size_t)blockIdx.x * blockDim.x + threadIdx.x;
    if (t >= (size_t)E_EDGES * (H / 4)) return;
    int e = (int)(t >> 6);   // H/4 = 64
    int q = (int)(t & 63);
    int s = src[e];
    int d = dst[e];
    float4 hv = ((const float4*)h)[(size_t)s * 64 + q];
    float4 cv = ((const float4*)c)[(size_t)s * 64 + q];
    float* hd = &g_hsum[(size_t)d * H + q * 4];
    float* cd = &g_csum[(size_t)d * H + q * 4];
    atomicAdd(hd + 0, hv.x); atomicAdd(hd + 1, hv.y);
    atomicAdd(hd + 2, hv.z); atomicAdd(hd + 3, hv.w);
    atomicAdd(cd + 0, cv.x); atomicAdd(cd + 1, cv.y);
    atomicAdd(cd + 2, cv.z); atomicAdd(cd + 3, cv.w);
}

// ---------------------------------------------------------------------------
// 4) SGEMM: g_pre[N,1024] = A[N,512] * g_B^T, where
//    A[n,k] = (k < 256) ? x[n,k] : g_hsum[n,k-256]
//    Tiles: BM=128, BN=128, BK=16; 256 threads; 8x8 microtile per thread.
//    grid.x = column blocks (8) so consecutive CTAs reuse the A row-tile in L2.
// ---------------------------------------------------------------------------
#define BM 128
#define BN 128
#define BK 16

__global__ __launch_bounds__(256, 2) void sgemm_kernel(const float* __restrict__ x) {
    __shared__ float As[BK][BM];
    __shared__ float Bs[BK][BN];

    const int cb = blockIdx.x;          // 0..7
    const int rb = blockIdx.y;          // row block
    const int row0 = rb * BM;
    const int col0 = cb * BN;
    const int tid = threadIdx.x;
    const int tx = tid & 15;            // 0..15 -> output cols tx*8..tx*8+7
    const int ty = tid >> 4;            // 0..15 -> output rows ty*8..ty*8+7

    float acc[8][8];
#pragma unroll
    for (int i = 0; i < 8; ++i)
#pragma unroll
        for (int j = 0; j < 8; ++j) acc[i][j] = 0.f;

#pragma unroll 1
    for (int kt = 0; kt < KDIM / BK; ++kt) {
        const float* Asrc = (kt * BK < 256) ? x : g_hsum;
        const int kbase = (kt * BK) & 255;

        // Cooperative loads: 512 float4 per tile per matrix, 2 per thread.
#pragma unroll
        for (int p = 0; p < 2; ++p) {
            int fidx = tid + 256 * p;       // 0..511
            int r = fidx >> 2;              // 0..127 tile row
            int kq = fidx & 3;              // float4 index along K
            // A tile (guard row OOB at the N tail)
            int grow = row0 + r;
            float4 av = make_float4(0.f, 0.f, 0.f, 0.f);
            if (grow < N_NODES)
                av = *(const float4*)&Asrc[(size_t)grow * 256 + kbase + kq * 4];
            As[kq * 4 + 0][r] = av.x;
            As[kq * 4 + 1][r] = av.y;
            As[kq * 4 + 2][r] = av.z;
            As[kq * 4 + 3][r] = av.w;
            // B tile (always in range: 8*128 == 1024)
            int jrow = col0 + r;
            float4 bv = *(const float4*)&g_B[(size_t)jrow * KDIM + kt * BK + kq * 4];
            Bs[kq * 4 + 0][r] = bv.x;
            Bs[kq * 4 + 1][r] = bv.y;
            Bs[kq * 4 + 2][r] = bv.z;
            Bs[kq * 4 + 3][r] = bv.w;
        }
        __syncthreads();

#pragma unroll
        for (int kk = 0; kk < BK; ++kk) {
            float a[8], b[8];
            *(float4*)&a[0] = *(const float4*)&As[kk][ty * 8];
            *(float4*)&a[4] = *(const float4*)&As[kk][ty * 8 + 4];
            *(float4*)&b[0] = *(const float4*)&Bs[kk][tx * 8];
            *(float4*)&b[4] = *(const float4*)&Bs[kk][tx * 8 + 4];
#pragma unroll
            for (int i = 0; i < 8; ++i)
#pragma unroll
                for (int j = 0; j < 8; ++j)
                    acc[i][j] += a[i] * b[j];
        }
        __syncthreads();
    }

    // Store pre-activations
#pragma unroll
    for (int i = 0; i < 8; ++i) {
        int grow = row0 + ty * 8 + i;
        if (grow >= N_NODES) break;
        float* dst = &g_pre[(size_t)grow * JDIM + col0 + tx * 8];
        *(float4*)&dst[0] = *(float4*)&acc[i][0];
        *(float4*)&dst[4] = *(float4*)&acc[i][4];
    }
}

// ---------------------------------------------------------------------------
// 5) Epilogue: gates + output. d_out = [h_new (N*256) | c_new (N*256)]
// ---------------------------------------------------------------------------
__global__ void epilogue_kernel(const float* __restrict__ b_iou,
                                const float* __restrict__ U_f_b,
                                float* __restrict__ out) {
    size_t t = (size_t)blockIdx.x * blockDim.x + threadIdx.x;
    if (t >= (size_t)N_NODES * H) return;
    size_t n = t >> 8;       // / 256
    int j = (int)(t & 255);
    const float* pre = &g_pre[n * JDIM];
    float iv = pre[j]        + b_iou[j];
    float ov = pre[256 + j]  + b_iou[256 + j];
    float uv = pre[512 + j]  + b_iou[512 + j];
    float fv = pre[768 + j]  + U_f_b[j];
    float cs = g_csum[n * H + j];

    float sig_i = 1.0f / (1.0f + expf(-iv));
    float sig_o = 1.0f / (1.0f + expf(-ov));
    float sig_f = 1.0f / (1.0f + expf(-fv));
    float c_new = sig_i * tanhf(uv) + sig_f * cs;
    float h_new = sig_o * tanhf(c_new);

    out[t] = h_new;
    out[(size_t)N_NODES * H + t] = c_new;
}

// ---------------------------------------------------------------------------
// kernel_launch
// Inputs (metadata order):
//  0: x [N,256] f32      1: h [N,256] f32    2: c [N,256] f32
//  3: src [E] i32        4: dst [E] i32
//  5: W_iou [768,256]    6: U_iou [768,256]  7: b_iou [1,768]
//  8: U_f_w [256,256]    9: U_f_b [256]
// Output: h_new [N,256] then c_new [N,256]
// ---------------------------------------------------------------------------
extern "C" void kernel_launch(void* const* d_in, const int* in_sizes, int n_in,
                              void* d_out, int out_size) {
    const float* x     = (const float*)d_in[0];
    const float* h     = (const float*)d_in[1];
    const float* c     = (const float*)d_in[2];
    const int*   src   = (const int*)d_in[3];
    const int*   dst   = (const int*)d_in[4];
    const float* W_iou = (const float*)d_in[5];
    const float* U_iou = (const float*)d_in[6];
    const float* b_iou = (const float*)d_in[7];
    const float* U_f_w = (const float*)d_in[8];
    const float* U_f_b = (const float*)d_in[9];
    float* out = (float*)d_out;

    // 1) combined weights
    build_B_kernel<<<(JDIM * KDIM + 255) / 256, 256>>>(W_iou, U_iou, U_f_w);

    // 2) zero accumulators
    {
        size_t n4 = (size_t)N_NODES * H / 4;
        zero_sums_kernel<<<(unsigned)((n4 + 255) / 256), 256>>>();
    }

    // 3) scatter-add children into parents
    {
        size_t nt = (size_t)E_EDGES * (H / 4);
        scatter_kernel<<<(unsigned)((nt + 255) / 256), 256>>>(h, c, src, dst);
    }

    // 4) fused GEMM (iou + f pre-activations)
    {
        dim3 grid(JDIM / BN, (N_NODES + BM - 1) / BM);
        sgemm_kernel<<<grid, 256>>>(x);
    }

    // 5) epilogue
    {
        size_t nt = (size_t)N_NODES * H;
        epilogue_kernel<<<(unsigned)((nt + 255) / 256), 256>>>(b_iou, U_f_b, out);
    }
}

// round 8
// speedup vs baseline: 2.1305x; 2.1305x over previous
#include <cuda_runtime.h>
#include <cuda_bf16.h>
#include <math.h>
#include <stdint.h>

// Problem constants
#define N_NODES 200000
#define E_EDGES 200000
#define H 256
#define KDIM 512     // combined K: [x | h_sum]
#define JDIM 1024    // combined output cols (permuted gate interleave)

// ---------------------------------------------------------------------------
// Scratch (static __device__ — no cudaMalloc anywhere)
// ---------------------------------------------------------------------------
__device__ float g_hsum[(size_t)N_NODES * H];          // 204.8 MB
__device__ float g_csum[(size_t)N_NODES * H];          // 204.8 MB
__device__ __nv_bfloat16 g_Bh[JDIM * KDIM];            // 1 MB (hi split, permuted rows)
__device__ __nv_bfloat16 g_Bl[JDIM * KDIM];            // 1 MB (lo split, permuted rows)

// ---------------------------------------------------------------------------
// 1) Split + permute weights into bf16 hi/lo. Permuted row jj = q*4 + g,
//    g in {0:i, 1:o, 2:u, 3:f}; cols k: [0,256)=W-part, [256,512)=U-part.
// ---------------------------------------------------------------------------
__global__ void build_B_kernel(const float* __restrict__ W_iou,
                               const float* __restrict__ U_iou,
                               const float* __restrict__ U_f_w) {
    int idx = blockIdx.x * blockDim.x + threadIdx.x;
    if (idx >= JDIM * KDIM) return;
    int jj = idx / KDIM;
    int k  = idx % KDIM;
    int q = jj >> 2;
    int g = jj & 3;
    float v;
    if (g < 3) {
        int row = g * 256 + q;
        v = (k < 256) ? W_iou[row * 256 + k] : U_iou[row * 256 + (k - 256)];
    } else {
        v = (k < 256) ? 0.0f : U_f_w[q * 256 + (k - 256)];
    }
    __nv_bfloat16 hi = __float2bfloat16(v);
    float lo = v - __bfloat162float(hi);
    g_Bh[idx] = hi;
    g_Bl[idx] = __float2bfloat16(lo);
}

// ---------------------------------------------------------------------------
// 2) Zero accumulators
// ---------------------------------------------------------------------------
__global__ void zero_sums_kernel() {
    size_t i = (size_t)blockIdx.x * blockDim.x + threadIdx.x;
    size_t n4 = (size_t)N_NODES * H / 4;
    if (i < n4) {
        ((float4*)g_hsum)[i] = make_float4(0.f, 0.f, 0.f, 0.f);
        ((float4*)g_csum)[i] = make_float4(0.f, 0.f, 0.f, 0.f);
    }
}

// ---------------------------------------------------------------------------
// 3) Scatter-add children into parents
// ---------------------------------------------------------------------------
__global__ void scatter_kernel(const float* __restrict__ h,
                               const float* __restrict__ c,
                               const int* __restrict__ src,
                               const int* __restrict__ dst) {
    size_t t = (size_t)blockIdx.x * blockDim.x + threadIdx.x;
    if (t >= (size_t)E_EDGES * (H / 4)) return;
    int e = (int)(t >> 6);
    int q = (int)(t & 63);
    int s = src[e];
    int d = dst[e];
    float4 hv = ((const float4*)h)[(size_t)s * 64 + q];
    float4 cv = ((const float4*)c)[(size_t)s * 64 + q];
    float* hd = &g_hsum[(size_t)d * H + q * 4];
    float* cd = &g_csum[(size_t)d * H + q * 4];
    atomicAdd(hd + 0, hv.x); atomicAdd(hd + 1, hv.y);
    atomicAdd(hd + 2, hv.z); atomicAdd(hd + 3, hv.w);
    atomicAdd(cd + 0, cv.x); atomicAdd(cd + 1, cv.y);
    atomicAdd(cd + 2, cv.z); atomicAdd(cd + 3, cv.w);
}

// ---------------------------------------------------------------------------
// 4) Fused warp-MMA (HMMA) GEMM + gate epilogue.
//    CTA tile 128 rows x 128 permuted cols (=32 h-cols x 4 gates).
//    K=512 in 8 slabs of 64. Per k-step: AhBh + AlBh + AhBl (error-comp bf16).
// ---------------------------------------------------------------------------
#define TBM 128
#define TBJ 128
#define BK  64
#define NSLAB (KDIM / BK)
#define APAD 72                 // halves per row (64 + 8 pad) -> conflict-free
#define SM_AH 0
#define SM_AL (SM_AH + TBM * APAD * 2)       // 18432
#define SM_BH (SM_AL + TBM * APAD * 2)       // 36864
#define SM_BL (SM_BH + TBJ * APAD * 2)       // 55296
#define SM_BYTES (SM_BL + TBJ * APAD * 2)    // 73728
#define PRELD 132               // floats per row in epilogue staging

__device__ __forceinline__ void mma16816(float* d, const uint32_t* a, const uint32_t* b) {
    asm volatile(
        "mma.sync.aligned.m16n8k16.row.col.f32.bf16.bf16.f32 "
        "{%0,%1,%2,%3}, {%4,%5,%6,%7}, {%8,%9}, {%0,%1,%2,%3};"
        : "+f"(d[0]), "+f"(d[1]), "+f"(d[2]), "+f"(d[3])
        : "r"(a[0]), "r"(a[1]), "r"(a[2]), "r"(a[3]), "r"(b[0]), "r"(b[1]));
}

__device__ __forceinline__ uint32_t pack_bf16x2(float a, float b) {
    __nv_bfloat162 t = __floats2bfloat162_rn(a, b);
    return *reinterpret_cast<uint32_t*>(&t);
}

__global__ __launch_bounds__(256, 2) void gemm_fused_kernel(
    const float* __restrict__ x,
    const float* __restrict__ b_iou,
    const float* __restrict__ U_f_b,
    float* __restrict__ out)
{
    extern __shared__ char smem[];
    __nv_bfloat16* sAh = (__nv_bfloat16*)(smem + SM_AH);
    __nv_bfloat16* sAl = (__nv_bfloat16*)(smem + SM_AL);
    __nv_bfloat16* sBh = (__nv_bfloat16*)(smem + SM_BH);
    __nv_bfloat16* sBl = (__nv_bfloat16*)(smem + SM_BL);

    const int tid = threadIdx.x;
    const int wid = tid >> 5;
    const int lid = tid & 31;
    const int gq = lid >> 2;       // quad-pair group 0..7
    const int tq = lid & 3;        // 0..3
    const int wm = wid >> 1;       // 0..3 : warp row block (32 rows)
    const int wn = wid & 1;        // 0..1 : warp col block (64 cols)
    const int cb = blockIdx.x;     // 0..7 : 32 h-cols each
    const int row0 = blockIdx.y * TBM;

    float acc[2][8][4];
#pragma unroll
    for (int m = 0; m < 2; ++m)
#pragma unroll
        for (int n = 0; n < 8; ++n)
#pragma unroll
            for (int v = 0; v < 4; ++v) acc[m][n][v] = 0.f;

#pragma unroll 1
    for (int slab = 0; slab < NSLAB; ++slab) {
        if (slab) __syncthreads();

        // --- A slab: 128x64 fp32 -> hi/lo bf16, padded SMEM ---
        // A's k-offset wraps at 256 because the source pointer switches to
        // g_hsum for slabs 4..7. B's k-offset does NOT wrap (combined [1024,512]).
        const float* Asrc = (slab < 4) ? x : g_hsum;
        const int kbA = (slab & 3) * BK;
        const int kbB = slab * BK;
#pragma unroll
        for (int it = 0; it < 8; ++it) {
            int f = tid + 256 * it;        // 0..2047
            int r = f >> 4;
            int kq = f & 15;
            int grow = row0 + r;
            float4 v = make_float4(0.f, 0.f, 0.f, 0.f);
            if (grow < N_NODES)
                v = *(const float4*)&Asrc[(size_t)grow * 256 + kbA + kq * 4];
            uint32_t h01 = pack_bf16x2(v.x, v.y);
            uint32_t h23 = pack_bf16x2(v.z, v.w);
            __nv_bfloat162 hh01 = *(__nv_bfloat162*)&h01;
            __nv_bfloat162 hh23 = *(__nv_bfloat162*)&h23;
            uint32_t l01 = pack_bf16x2(v.x - __bfloat162float(hh01.x),
                                       v.y - __bfloat162float(hh01.y));
            uint32_t l23 = pack_bf16x2(v.z - __bfloat162float(hh23.x),
                                       v.w - __bfloat162float(hh23.y));
            int o = r * APAD + kq * 4;
            *(uint2*)&sAh[o] = make_uint2(h01, h23);
            *(uint2*)&sAl[o] = make_uint2(l01, l23);
        }

        // --- B slab: pre-split bf16 hi/lo, 128 rows x 64 halves each ---
#pragma unroll
        for (int it = 0; it < 8; ++it) {
            int f = tid + 256 * it;        // 0..2047 ; [0,1024)=hi, [1024,2048)=lo
            int r = (f >> 3) & 127;
            int kq = f & 7;
            const __nv_bfloat16* src = (f < 1024) ? g_Bh : g_Bl;
            __nv_bfloat16* dstp = (f < 1024) ? sBh : sBl;
            uint4 v = *(const uint4*)&src[(size_t)(cb * TBJ + r) * KDIM + kbB + kq * 8];
            *(uint4*)&dstp[r * APAD + kq * 8] = v;
        }
        __syncthreads();

        // --- MMA over 4 k-steps of 16 ---
#pragma unroll
        for (int ks = 0; ks < 4; ++ks) {
            const int ko = ks * 16 + tq * 2;
            uint32_t afr[2][4], al[2][4], bfr[8][2];
            // Ah fragments
#pragma unroll
            for (int m = 0; m < 2; ++m) {
                int rb = wm * 32 + m * 16 + gq;
                afr[m][0] = *(const uint32_t*)&sAh[rb * APAD + ko];
                afr[m][1] = *(const uint32_t*)&sAh[(rb + 8) * APAD + ko];
                afr[m][2] = *(const uint32_t*)&sAh[rb * APAD + ko + 8];
                afr[m][3] = *(const uint32_t*)&sAh[(rb + 8) * APAD + ko + 8];
            }
            // Bh fragments
#pragma unroll
            for (int n = 0; n < 8; ++n) {
                int cc = wn * 64 + n * 8 + gq;
                bfr[n][0] = *(const uint32_t*)&sBh[cc * APAD + ko];
                bfr[n][1] = *(const uint32_t*)&sBh[cc * APAD + ko + 8];
            }
            // pass 1: Ah * Bh
#pragma unroll
            for (int m = 0; m < 2; ++m)
#pragma unroll
                for (int n = 0; n < 8; ++n)
                    mma16816(acc[m][n], afr[m], bfr[n]);
            // Al fragments, pass 2: Al * Bh
#pragma unroll
            for (int m = 0; m < 2; ++m) {
                int rb = wm * 32 + m * 16 + gq;
                al[m][0] = *(const uint32_t*)&sAl[rb * APAD + ko];
                al[m][1] = *(const uint32_t*)&sAl[(rb + 8) * APAD + ko];
                al[m][2] = *(const uint32_t*)&sAl[rb * APAD + ko + 8];
                al[m][3] = *(const uint32_t*)&sAl[(rb + 8) * APAD + ko + 8];
            }
#pragma unroll
            for (int m = 0; m < 2; ++m)
#pragma unroll
                for (int n = 0; n < 8; ++n)
                    mma16816(acc[m][n], al[m], bfr[n]);
            // Bl fragments (overwrite), pass 3: Ah * Bl
#pragma unroll
            for (int n = 0; n < 8; ++n) {
                int cc = wn * 64 + n * 8 + gq;
                bfr[n][0] = *(const uint32_t*)&sBl[cc * APAD + ko];
                bfr[n][1] = *(const uint32_t*)&sBl[cc * APAD + ko + 8];
            }
#pragma unroll
            for (int m = 0; m < 2; ++m)
#pragma unroll
                for (int n = 0; n < 8; ++n)
                    mma16816(acc[m][n], afr[m], bfr[n]);
        }
    }

    // --- stage accumulators into SMEM (overlays tile buffers) ---
    __syncthreads();
    float* pre = (float*)smem;     // [128][PRELD]
#pragma unroll
    for (int m = 0; m < 2; ++m)
#pragma unroll
        for (int n = 0; n < 8; ++n) {
            int r = wm * 32 + m * 16 + gq;
            int cc = wn * 64 + n * 8 + tq * 2;
            *(float2*)&pre[r * PRELD + cc] = make_float2(acc[m][n][0], acc[m][n][1]);
            *(float2*)&pre[(r + 8) * PRELD + cc] = make_float2(acc[m][n][2], acc[m][n][3]);
        }
    __syncthreads();

    // --- gate epilogue + coalesced stores ---
    const int q = tid & 31;
    const int Q = cb * 32 + q;
    const float bi = __ldg(&b_iou[Q]);
    const float bo = __ldg(&b_iou[256 + Q]);
    const float bu = __ldg(&b_iou[512 + Q]);
    const float bf = __ldg(&U_f_b[Q]);
#pragma unroll
    for (int i = 0; i < 16; ++i) {
        int r = (tid >> 5) + 8 * i;
        int grow = row0 + r;
        if (grow >= N_NODES) continue;
        float4 p = *(const float4*)&pre[r * PRELD + q * 4];   // {i,o,u,f}
        float iv = p.x + bi;
        float ov = p.y + bo;
        float uv = p.z + bu;
        float fv = p.w + bf;
        float cs = g_csum[(size_t)grow * 256 + Q];
        float sig_i = 1.0f / (1.0f + __expf(-iv));
        float sig_o = 1.0f / (1.0f + __expf(-ov));
        float sig_f = 1.0f / (1.0f + __expf(-fv));
        float c_new = sig_i * tanhf(uv) + sig_f * cs;
        float h_new = sig_o * tanhf(c_new);
        out[(size_t)grow * 256 + Q] = h_new;
        out[(size_t)N_NODES * 256 + (size_t)grow * 256 + Q] = c_new;
    }
}

// ---------------------------------------------------------------------------
// kernel_launch
// ---------------------------------------------------------------------------
extern "C" void kernel_launch(void* const* d_in, const int* in_sizes, int n_in,
                              void* d_out, int out_size) {
    const float* x     = (const float*)d_in[0];
    const float* h     = (const float*)d_in[1];
    const float* c     = (const float*)d_in[2];
    const int*   src   = (const int*)d_in[3];
    const int*   dst   = (const int*)d_in[4];
    const float* W_iou = (const float*)d_in[5];
    const float* U_iou = (const float*)d_in[6];
    const float* b_iou = (const float*)d_in[7];
    const float* U_f_w = (const float*)d_in[8];
    const float* U_f_b = (const float*)d_in[9];
    float* out = (float*)d_out;

    cudaFuncSetAttribute(gemm_fused_kernel,
                         cudaFuncAttributeMaxDynamicSharedMemorySize, SM_BYTES);

    build_B_kernel<<<(JDIM * KDIM + 255) / 256, 256>>>(W_iou, U_iou, U_f_w);

    {
        size_t n4 = (size_t)N_NODES * H / 4;
        zero_sums_kernel<<<(unsigned)((n4 + 255) / 256), 256>>>();
    }
    {
        size_t nt = (size_t)E_EDGES * (H / 4);
        scatter_kernel<<<(unsigned)((nt + 255) / 256), 256>>>(h, c, src, dst);
    }
    {
        dim3 grid(JDIM / TBJ, (N_NODES + TBM - 1) / TBM);   // (8, 1563)
        gemm_fused_kernel<<<grid, 256, SM_BYTES>>>(x, b_iou, U_f_b, out);
    }
}